// round 2
// baseline (speedup 1.0000x reference)
#include <cuda_runtime.h>
#include <math.h>

#define B_  4
#define S_  2048
#define SV_ 50
#define E_  1024

// ---------------- scratch (device globals; no allocation allowed) ----------
__device__ float g_q [B_*S_*E_];
__device__ float g_k [B_*S_*E_];
__device__ float g_q2[B_*S_*E_];
__device__ float g_k2[B_*S_*E_];
__device__ float g_v [B_*SV_*E_];
__device__ float g_vq[B_*S_*SV_];
__device__ float g_vk[B_*S_*SV_];
__device__ float g_cs [B_*E_];
__device__ float g_cs2[B_*E_];

// ---------------- generic guarded batched SGEMM ----------------------------
// C[b] = alpha * op(A[b]) @ op(B[b]) (+ beta*C[b]) (+ bias[b][n])
// A: [M,K] row-major (optionally tanh applied elementwise)
// B: NN -> [K,N] row-major ; NT -> [N,K] row-major (computes A @ B^T)
// C: [M,N] row-major
template<bool TANH_A, bool TRANS_B, bool BETA, bool BIAS>
__global__ __launch_bounds__(256, 2)
void gemm_k(const float* __restrict__ A, const float* __restrict__ Bm,
            float* __restrict__ C, const float* __restrict__ bias,
            int M, int N, int K,
            long long sA, long long sB, long long sC, long long sBias,
            float alpha, float beta)
{
    constexpr int BM = 128, BN = 128, BK = 16;
    __shared__ float As[2][BK][BM + 4];
    __shared__ float Bs[2][BK][BN + 4];

    A  += (long long)blockIdx.z * sA;
    Bm += (long long)blockIdx.z * sB;
    C  += (long long)blockIdx.z * sC;
    const float* biasp = nullptr;
    if (BIAS) biasp = bias + (long long)blockIdx.z * sBias;

    const int tid  = threadIdx.x;
    const int warp = tid >> 5, lane = tid & 31;
    const int wr = warp & 3, wc = warp >> 2;   // 4x2 warp grid (32x64 each)
    const int lr = lane >> 3, lc = lane & 7;   // 4x8 lanes (8x8 each)
    const int m0 = wr * 32 + lr * 8;
    const int n0 = wc * 64 + lc * 8;

    const int bm = blockIdx.y * BM;
    const int bn = blockIdx.x * BN;

    float acc[8][8];
#pragma unroll
    for (int i = 0; i < 8; i++)
#pragma unroll
        for (int j = 0; j < 8; j++) acc[i][j] = 0.f;

    const int nt = (K + BK - 1) / BK;
    float ra[8], rb[8];

    auto loadA = [&](int kt) {
#pragma unroll
        for (int i = 0; i < 8; i++) {
            int idx = i * 256 + tid;
            int row = idx >> 4, kk = idx & 15;
            int gm = bm + row, gk = kt * BK + kk;
            float v = 0.f;
            if (gm < M && gk < K) v = A[(long long)gm * K + gk];
            if (TANH_A) v = tanhf(v);
            ra[i] = v;
        }
    };
    auto loadB = [&](int kt) {
#pragma unroll
        for (int i = 0; i < 8; i++) {
            int idx = i * 256 + tid;
            float v = 0.f;
            if (!TRANS_B) {
                int kk = idx >> 7, n = idx & 127;
                int gk = kt * BK + kk, gn = bn + n;
                if (gk < K && gn < N) v = Bm[(long long)gk * N + gn];
            } else {
                int n = idx >> 4, kk = idx & 15;
                int gn = bn + n, gk = kt * BK + kk;
                if (gn < N && gk < K) v = Bm[(long long)gn * K + gk];
            }
            rb[i] = v;
        }
    };
    auto storeA = [&](int buf) {
#pragma unroll
        for (int i = 0; i < 8; i++) {
            int idx = i * 256 + tid;
            As[buf][idx & 15][idx >> 4] = ra[i];
        }
    };
    auto storeB = [&](int buf) {
#pragma unroll
        for (int i = 0; i < 8; i++) {
            int idx = i * 256 + tid;
            if (!TRANS_B) Bs[buf][idx >> 7][idx & 127] = rb[i];
            else          Bs[buf][idx & 15][idx >> 4]  = rb[i];
        }
    };

    loadA(0); loadB(0); storeA(0); storeB(0);
    __syncthreads();

    for (int kt = 0; kt < nt; ++kt) {
        const int cur = kt & 1;
        if (kt + 1 < nt) { loadA(kt + 1); loadB(kt + 1); }
#pragma unroll
        for (int kk = 0; kk < BK; ++kk) {
            float af[8], bf[8];
#pragma unroll
            for (int i = 0; i < 8; i++) af[i] = As[cur][kk][m0 + i];
#pragma unroll
            for (int j = 0; j < 8; j++) bf[j] = Bs[cur][kk][n0 + j];
#pragma unroll
            for (int i = 0; i < 8; i++)
#pragma unroll
                for (int j = 0; j < 8; j++) acc[i][j] += af[i] * bf[j];
        }
        if (kt + 1 < nt) { storeA(cur ^ 1); storeB(cur ^ 1); }
        __syncthreads();
    }

#pragma unroll
    for (int i = 0; i < 8; i++) {
        int gm = bm + m0 + i;
        if (gm < M) {
#pragma unroll
            for (int j = 0; j < 8; j++) {
                int gn = bn + n0 + j;
                if (gn < N) {
                    float v = alpha * acc[i][j];
                    if (BETA) v += beta * C[(long long)gm * N + gn];
                    if (BIAS) v += biasp[gn];
                    C[(long long)gm * N + gn] = v;
                }
            }
        }
    }
}

// ---------------- softmax over rows (in place) ------------------------------
__global__ void softmax_kernel(float* __restrict__ x, int cols)
{
    long long row = blockIdx.x;
    float* p = x + row * (long long)cols;
    __shared__ float red[256];
    int t = threadIdx.x;

    float mx = -INFINITY;
    for (int c = t; c < cols; c += 256) mx = fmaxf(mx, p[c]);
    red[t] = mx; __syncthreads();
    for (int s = 128; s > 0; s >>= 1) {
        if (t < s) red[t] = fmaxf(red[t], red[t + s]);
        __syncthreads();
    }
    mx = red[0]; __syncthreads();

    float sum = 0.f;
    for (int c = t; c < cols; c += 256) {
        float e = expf(p[c] - mx);
        p[c] = e;
        sum += e;
    }
    red[t] = sum; __syncthreads();
    for (int s = 128; s > 0; s >>= 1) {
        if (t < s) red[t] += red[t + s];
        __syncthreads();
    }
    float inv = 1.f / red[0];
    for (int c = t; c < cols; c += 256) p[c] *= inv;
}

// ---------------- column sum: out[b,e] = sum_t x[b,t,e] ---------------------
__global__ void colsum_kernel(const float* __restrict__ x, float* __restrict__ out,
                              int T, int E)
{
    int e = blockIdx.x * blockDim.x + threadIdx.x;
    int b = blockIdx.y;
    const float* p = x + (long long)b * T * E + e;
    float s = 0.f;
    for (int t = 0; t < T; t++) s += p[(long long)t * E];
    out[(long long)b * E + e] = s;
}

// ---------------- host launcher ---------------------------------------------
extern "C" void kernel_launch(void* const* d_in, const int* in_sizes, int n_in,
                              void* d_out, int out_size)
{
    const float* Q    = (const float*)d_in[0];
    const float* K    = (const float*)d_in[1];
    const float* V    = (const float*)d_in[2];
    const float* W_Q  = (const float*)d_in[3];
    const float* W_K  = (const float*)d_in[4];
    const float* W_v  = (const float*)d_in[5];
    const float* W_vq = (const float*)d_in[6];
    const float* W_vk = (const float*)d_in[7];

    float* out  = (float*)d_out;
    float* outQ = out;                                  // [B,S,E]
    float* outK = out + (long long)B_ * S_ * E_;        // [B,S,E]
    float* f    = out + 2ll * B_ * S_ * E_;             // [B,S,S]

    float *q, *k, *v, *q2, *k2, *vq, *vk, *cs, *cs2;
    cudaGetSymbolAddress((void**)&q,   g_q);
    cudaGetSymbolAddress((void**)&k,   g_k);
    cudaGetSymbolAddress((void**)&v,   g_v);
    cudaGetSymbolAddress((void**)&q2,  g_q2);
    cudaGetSymbolAddress((void**)&k2,  g_k2);
    cudaGetSymbolAddress((void**)&vq,  g_vq);
    cudaGetSymbolAddress((void**)&vk,  g_vk);
    cudaGetSymbolAddress((void**)&cs,  g_cs);
    cudaGetSymbolAddress((void**)&cs2, g_cs2);

    const float inv = 1.0f / 32.0f;   // 1/sqrt(1024)
    const long long sQE = (long long)S_ * E_;
    const long long sSS = (long long)S_ * S_;
    const long long sSV = (long long)S_ * SV_;
    dim3 blk(256);

    // projections: q = tanh(Q)@W_Q, k = tanh(K)@W_K  (M=B*S flattened, W shared)
    gemm_k<true,false,false,false><<<dim3(8,64,1),blk>>>(Q, W_Q, q, nullptr,
        B_*S_, E_, E_, 0,0,0,0, 1.f, 0.f);
    gemm_k<true,false,false,false><<<dim3(8,64,1),blk>>>(K, W_K, k, nullptr,
        B_*S_, E_, E_, 0,0,0,0, 1.f, 0.f);
    // v = tanh(V)@W_v  (M = B*SV = 200)
    gemm_k<true,false,false,false><<<dim3(8,2,1),blk>>>(V, W_v, v, nullptr,
        B_*SV_, E_, E_, 0,0,0,0, 1.f, 0.f);

    // scores -> f region of d_out: f = (q @ k^T)/32, then softmax in place
    gemm_k<false,true,false,false><<<dim3(16,16,B_),blk>>>(q, k, f, nullptr,
        S_, S_, E_, sQE, sQE, sSS, 0, inv, 0.f);
    softmax_kernel<<<B_*S_, 256>>>(f, S_);

    // vq = q@v^T/32, vk = k@v^T/32   [B,S,SV]
    gemm_k<false,true,false,false><<<dim3(1,16,B_),blk>>>(q, v, vq, nullptr,
        S_, SV_, E_, sQE, (long long)SV_*E_, sSV, 0, inv, 0.f);
    gemm_k<false,true,false,false><<<dim3(1,16,B_),blk>>>(k, v, vk, nullptr,
        S_, SV_, E_, sQE, (long long)SV_*E_, sSV, 0, inv, 0.f);

    // colsum_k[b,e] = sum_t k[b,t,e]   (g@x = colsum(x) - f@x)
    colsum_kernel<<<dim3(E_/256, B_), 256>>>(k, cs, S_, E_);

    // q2 = vq@W_vq ; k2 = vk@W_vk + colsum_k
    gemm_k<false,false,false,false><<<dim3(8,16,B_),blk>>>(vq, W_vq, q2, nullptr,
        S_, E_, SV_, sSV, 0, sQE, 0, 1.f, 0.f);
    gemm_k<false,false,false,true><<<dim3(8,16,B_),blk>>>(vk, W_vk, k2, cs,
        S_, E_, SV_, sSV, 0, sQE, E_, 1.f, 0.f);

    // q2 += f@q ; k2 += -f@k
    gemm_k<false,false,true,false><<<dim3(8,16,B_),blk>>>(f, q, q2, nullptr,
        S_, E_, S_, sSS, sQE, sQE, 0, 1.f, 1.f);
    gemm_k<false,false,true,false><<<dim3(8,16,B_),blk>>>(f, k, k2, nullptr,
        S_, E_, S_, sSS, sQE, sQE, 0, -1.f, 1.f);

    colsum_kernel<<<dim3(E_/256, B_), 256>>>(k2, cs2, S_, E_);

    // Q_out = f@q2 ; K_out = colsum_k2 - f@k2
    gemm_k<false,false,false,false><<<dim3(8,16,B_),blk>>>(f, q2, outQ, nullptr,
        S_, E_, S_, sSS, sQE, sQE, 0, 1.f, 0.f);
    gemm_k<false,false,false,true><<<dim3(8,16,B_),blk>>>(f, k2, outK, cs2,
        S_, E_, S_, sSS, sQE, sQE, E_, -1.f, 0.f);

    (void)in_sizes; (void)n_in; (void)out_size;
}

// round 4
// speedup vs baseline: 2.1036x; 2.1036x over previous
#include <cuda_runtime.h>
#include <cuda_bf16.h>
#include <math.h>
#include <stdint.h>

#define B_  4
#define S_  2048
#define SV_ 50
#define E_  1024

// ---------------- scratch (device globals) ---------------------------------
__device__ float g_q [B_*S_*E_];
__device__ float g_k [B_*S_*E_];
__device__ float g_q2[B_*S_*E_];
__device__ float g_k2[B_*S_*E_];
__device__ float g_v [B_*SV_*E_];
__device__ float g_vq[B_*S_*SV_];
__device__ float g_vk[B_*S_*SV_];
__device__ float g_cs [B_*E_];
__device__ float g_cs2[B_*E_];

__device__ __nv_bfloat16 g_Qs_h[B_*S_*E_], g_Qs_l[B_*S_*E_];
__device__ __nv_bfloat16 g_Ks_h[B_*S_*E_], g_Ks_l[B_*S_*E_];
__device__ __nv_bfloat16 g_WqT_h[E_*E_],  g_WqT_l[E_*E_];
__device__ __nv_bfloat16 g_WkT_h[E_*E_],  g_WkT_l[E_*E_];
__device__ __nv_bfloat16 g_qh[B_*S_*E_],  g_ql[B_*S_*E_];
__device__ __nv_bfloat16 g_kh[B_*S_*E_],  g_kl[B_*S_*E_];
__device__ __nv_bfloat16 g_qTh[B_*S_*E_], g_qTl[B_*S_*E_];
__device__ __nv_bfloat16 g_kTh[B_*S_*E_], g_kTl[B_*S_*E_];
__device__ __nv_bfloat16 g_fh[(size_t)B_*S_*S_], g_fl[(size_t)B_*S_*S_];
__device__ __nv_bfloat16 g_q2Th[B_*S_*E_], g_q2Tl[B_*S_*E_];
__device__ __nv_bfloat16 g_k2Th[B_*S_*E_], g_k2Tl[B_*S_*E_];

// ---------------- PTX helpers -----------------------------------------------
__device__ __forceinline__ uint32_t smem_u32(const void* p) {
    uint32_t a;
    asm("{ .reg .u64 t; cvta.to.shared.u64 t, %1; cvt.u32.u64 %0, t; }"
        : "=r"(a) : "l"(p));
    return a;
}
__device__ __forceinline__ void cp_async16(uint32_t dst, const void* src) {
    asm volatile("cp.async.cg.shared.global [%0], [%1], 16;"
                 :: "r"(dst), "l"(src) : "memory");
}
#define CP_COMMIT() asm volatile("cp.async.commit_group;" ::: "memory")
#define CP_WAIT(n)  asm volatile("cp.async.wait_group %0;" :: "n"(n) : "memory")

#define LDMATRIX_X4(r0, r1, r2, r3, addr) \
    asm volatile("ldmatrix.sync.aligned.m8n8.x4.shared.b16 {%0,%1,%2,%3}, [%4];" \
        : "=r"(r0), "=r"(r1), "=r"(r2), "=r"(r3) : "r"(addr))

#define MMA_BF16(d, a, b) \
    asm volatile("mma.sync.aligned.m16n8k16.row.col.f32.bf16.bf16.f32 " \
        "{%0,%1,%2,%3},{%4,%5,%6,%7},{%8,%9},{%0,%1,%2,%3};" \
        : "+f"((d)[0]), "+f"((d)[1]), "+f"((d)[2]), "+f"((d)[3]) \
        : "r"((a)[0]), "r"((a)[1]), "r"((a)[2]), "r"((a)[3]), \
          "r"((b)[0]), "r"((b)[1]))

// ---------------- bf16x3 HMMA NT GEMM ---------------------------------------
// C[z] = alpha * (Ah+Al)[M,K] @ (Bh+Bl)[N,K]^T (+ beta*C) (+ bias[n])
// Requires M%128==0, N%128==0, K%32==0 (all call sites satisfy this).
constexpr int HM_BM = 128, HM_BN = 128, HM_BK = 32;
constexpr int HM_LDS = HM_BK + 8;            // padded row (elements)
constexpr int HM_TILE = HM_BM * HM_LDS;      // 5120 elems per tensor-half
constexpr int HM_BUF = 4 * HM_TILE;          // Ah,Al,Bh,Bl per buffer
constexpr int HM_SMEM_BYTES = 2 * HM_BUF * 2; // 81920

template<bool BETA, bool BIAS>
__global__ void __launch_bounds__(256)
hmma_nt(const __nv_bfloat16* __restrict__ Ah, const __nv_bfloat16* __restrict__ Al,
        const __nv_bfloat16* __restrict__ Bh, const __nv_bfloat16* __restrict__ Bl,
        float* __restrict__ C, const float* __restrict__ bias,
        int M, int N, int K,
        long long sA, long long sB, long long sC, long long sBias,
        float alpha, float beta)
{
    extern __shared__ __nv_bfloat16 sm[];
    const uint32_t sbase = smem_u32(sm);

    Ah += blockIdx.z * sA;  Al += blockIdx.z * sA;
    Bh += blockIdx.z * sB;  Bl += blockIdx.z * sB;
    C  += blockIdx.z * sC;
    const float* bp = BIAS ? (bias + blockIdx.z * sBias) : nullptr;

    const int tid = threadIdx.x;
    const int warp = tid >> 5, lane = tid & 31;
    const int wm = warp & 3, wn = warp >> 2;         // 4x2 warps: 32m x 64n each
    const int bm = blockIdx.y * HM_BM;
    const int bn = blockIdx.x * HM_BN;

    // chunk mapping for cp.async: 512 chunks (16B) per tensor-half per buffer
    const int c0 = tid, c1 = tid + 256;
    const int r0c = c0 >> 2, e0c = (c0 & 3) * 8;
    const int r1c = c1 >> 2, e1c = (c1 & 3) * 8;

    auto issue = [&](int it, int buf) {
        const long long ko = (long long)it * HM_BK;
        const uint32_t bofs = (uint32_t)buf * HM_BUF;
        // A hi/lo
        {
            uint32_t d0 = sbase + (bofs + r0c * HM_LDS + e0c) * 2;
            uint32_t d1 = sbase + (bofs + r1c * HM_LDS + e1c) * 2;
            cp_async16(d0,             Ah + (long long)(bm + r0c) * K + ko + e0c);
            cp_async16(d1,             Ah + (long long)(bm + r1c) * K + ko + e1c);
            cp_async16(d0 + HM_TILE*2, Al + (long long)(bm + r0c) * K + ko + e0c);
            cp_async16(d1 + HM_TILE*2, Al + (long long)(bm + r1c) * K + ko + e1c);
        }
        // B hi/lo
        {
            uint32_t d0 = sbase + (bofs + 2*HM_TILE + r0c * HM_LDS + e0c) * 2;
            uint32_t d1 = sbase + (bofs + 2*HM_TILE + r1c * HM_LDS + e1c) * 2;
            cp_async16(d0,             Bh + (long long)(bn + r0c) * K + ko + e0c);
            cp_async16(d1,             Bh + (long long)(bn + r1c) * K + ko + e1c);
            cp_async16(d0 + HM_TILE*2, Bl + (long long)(bn + r0c) * K + ko + e0c);
            cp_async16(d1 + HM_TILE*2, Bl + (long long)(bn + r1c) * K + ko + e1c);
        }
    };

    float acc[2][8][4];
#pragma unroll
    for (int m = 0; m < 2; m++)
#pragma unroll
        for (int n = 0; n < 8; n++)
#pragma unroll
            for (int j = 0; j < 4; j++) acc[m][n][j] = 0.f;

    const int NT = K / HM_BK;
    issue(0, 0); CP_COMMIT();

    const int lr  = lane & 15;
    const int lc8 = (lane >> 4) << 3;

    for (int kt = 0; kt < NT; ++kt) {
        const int buf = kt & 1;
        if (kt + 1 < NT) { issue(kt + 1, buf ^ 1); CP_COMMIT(); CP_WAIT(1); }
        else             { CP_WAIT(0); }
        __syncthreads();

        const uint32_t aofs = (uint32_t)buf * HM_BUF;
#pragma unroll
        for (int ks = 0; ks < 2; ks++) {
            const int k0 = ks * 16;
            uint32_t fAh[2][4], fAl[2][4], fB[8][2];
            // A hi fragments (2 m16 tiles)
#pragma unroll
            for (int t = 0; t < 2; t++) {
                uint32_t a = sbase + (aofs + (uint32_t)(wm*32 + t*16 + lr) * HM_LDS + k0 + lc8) * 2;
                LDMATRIX_X4(fAh[t][0], fAh[t][1], fAh[t][2], fAh[t][3], a);
            }
            // B hi fragments (4 n16 pairs -> 8 n8 tiles)
#pragma unroll
            for (int p = 0; p < 4; p++) {
                uint32_t a = sbase + (aofs + 2*HM_TILE + (uint32_t)(wn*64 + p*16 + lr) * HM_LDS + k0 + lc8) * 2;
                uint32_t r0, r1, r2, r3;
                LDMATRIX_X4(r0, r1, r2, r3, a);
                fB[p*2][0]   = r0; fB[p*2][1]   = r2;
                fB[p*2+1][0] = r1; fB[p*2+1][1] = r3;
            }
            // hh
#pragma unroll
            for (int m = 0; m < 2; m++)
#pragma unroll
                for (int n = 0; n < 8; n++) MMA_BF16(acc[m][n], fAh[m], fB[n]);
            // A lo fragments
#pragma unroll
            for (int t = 0; t < 2; t++) {
                uint32_t a = sbase + (aofs + HM_TILE + (uint32_t)(wm*32 + t*16 + lr) * HM_LDS + k0 + lc8) * 2;
                LDMATRIX_X4(fAl[t][0], fAl[t][1], fAl[t][2], fAl[t][3], a);
            }
            // lh: Al x Bh
#pragma unroll
            for (int m = 0; m < 2; m++)
#pragma unroll
                for (int n = 0; n < 8; n++) MMA_BF16(acc[m][n], fAl[m], fB[n]);
            // B lo fragments (overwrite fB)
#pragma unroll
            for (int p = 0; p < 4; p++) {
                uint32_t a = sbase + (aofs + 3*HM_TILE + (uint32_t)(wn*64 + p*16 + lr) * HM_LDS + k0 + lc8) * 2;
                uint32_t r0, r1, r2, r3;
                LDMATRIX_X4(r0, r1, r2, r3, a);
                fB[p*2][0]   = r0; fB[p*2][1]   = r2;
                fB[p*2+1][0] = r1; fB[p*2+1][1] = r3;
            }
            // hl: Ah x Bl
#pragma unroll
            for (int m = 0; m < 2; m++)
#pragma unroll
                for (int n = 0; n < 8; n++) MMA_BF16(acc[m][n], fAh[m], fB[n]);
        }
        __syncthreads();
    }

    // epilogue
    const int qr = lane >> 2, qc = (lane & 3) * 2;
#pragma unroll
    for (int m = 0; m < 2; m++) {
#pragma unroll
        for (int n = 0; n < 8; n++) {
            const int col = bn + wn*64 + n*8 + qc;
#pragma unroll
            for (int h = 0; h < 2; h++) {
                const int row = bm + wm*32 + m*16 + qr + h*8;
                float2 v;
                v.x = alpha * acc[m][n][h*2 + 0];
                v.y = alpha * acc[m][n][h*2 + 1];
                float2* cp = (float2*)(C + (long long)row * N + col);
                if (BETA) {
                    float2 c0v = *cp;
                    v.x += beta * c0v.x; v.y += beta * c0v.y;
                }
                if (BIAS) {
                    v.x += bp[col]; v.y += bp[col + 1];
                }
                *cp = v;
            }
        }
    }
}

// ---------------- split kernels ---------------------------------------------
template<bool TANH>
__global__ void split_k(const float* __restrict__ x, __nv_bfloat16* __restrict__ h,
                        __nv_bfloat16* __restrict__ l, long long n)
{
    long long i = ((long long)blockIdx.x * blockDim.x + threadIdx.x) * 4;
    if (i >= n) return;
    float4 v = *(const float4*)(x + i);
    if (TANH) { v.x = tanhf(v.x); v.y = tanhf(v.y); v.z = tanhf(v.z); v.w = tanhf(v.w); }
    __nv_bfloat16 h0 = __float2bfloat16(v.x), h1 = __float2bfloat16(v.y);
    __nv_bfloat16 h2 = __float2bfloat16(v.z), h3 = __float2bfloat16(v.w);
    __nv_bfloat16 l0 = __float2bfloat16(v.x - __bfloat162float(h0));
    __nv_bfloat16 l1 = __float2bfloat16(v.y - __bfloat162float(h1));
    __nv_bfloat16 l2 = __float2bfloat16(v.z - __bfloat162float(h2));
    __nv_bfloat16 l3 = __float2bfloat16(v.w - __bfloat162float(h3));
    __nv_bfloat162* hp = (__nv_bfloat162*)(h + i);
    __nv_bfloat162* lp = (__nv_bfloat162*)(l + i);
    hp[0] = __nv_bfloat162(h0, h1); hp[1] = __nv_bfloat162(h2, h3);
    lp[0] = __nv_bfloat162(l0, l1); lp[1] = __nv_bfloat162(l2, l3);
}

// transpose + split: in [R,C] -> out [C,R] bf16 hi/lo (batched)
__global__ void splitT_k(const float* __restrict__ x, __nv_bfloat16* __restrict__ h,
                         __nv_bfloat16* __restrict__ l, int R, int C,
                         long long sIn, long long sOut)
{
    __shared__ float t[32][33];
    const float* xb = x + blockIdx.z * sIn;
    int r0 = blockIdx.y * 32, c0 = blockIdx.x * 32;
#pragma unroll
    for (int i = 0; i < 4; i++) {
        int r = r0 + threadIdx.y + i * 8;
        t[threadIdx.y + i * 8][threadIdx.x] = xb[(long long)r * C + c0 + threadIdx.x];
    }
    __syncthreads();
#pragma unroll
    for (int i = 0; i < 4; i++) {
        int c = c0 + threadIdx.y + i * 8;
        float v = t[threadIdx.x][threadIdx.y + i * 8];
        long long o = blockIdx.z * sOut + (long long)c * R + r0 + threadIdx.x;
        __nv_bfloat16 hh = __float2bfloat16(v);
        h[o] = hh;
        l[o] = __float2bfloat16(v - __bfloat162float(hh));
    }
}

// ---------------- SIMT SGEMM (small GEMMs only) -----------------------------
template<bool TANH_A, bool TRANS_B, bool BETA, bool BIAS>
__global__ __launch_bounds__(256, 2)
void gemm_k(const float* __restrict__ A, const float* __restrict__ Bm,
            float* __restrict__ C, const float* __restrict__ bias,
            int M, int N, int K,
            long long sA, long long sB, long long sC, long long sBias,
            float alpha, float beta)
{
    constexpr int BM = 128, BN = 128, BK = 16;
    __shared__ float As[2][BK][BM + 4];
    __shared__ float Bs[2][BK][BN + 4];

    A  += (long long)blockIdx.z * sA;
    Bm += (long long)blockIdx.z * sB;
    C  += (long long)blockIdx.z * sC;
    const float* biasp = nullptr;
    if (BIAS) biasp = bias + (long long)blockIdx.z * sBias;

    const int tid = threadIdx.x;
    const int warp = tid >> 5, lane = tid & 31;
    const int wr = warp & 3, wc = warp >> 2;
    const int lr = lane >> 3, lc = lane & 7;
    const int m0 = wr * 32 + lr * 8;
    const int n0 = wc * 64 + lc * 8;
    const int bm = blockIdx.y * BM;
    const int bn = blockIdx.x * BN;

    float acc[8][8];
#pragma unroll
    for (int i = 0; i < 8; i++)
#pragma unroll
        for (int j = 0; j < 8; j++) acc[i][j] = 0.f;

    const int nt = (K + BK - 1) / BK;
    float ra[8], rb[8];

    auto loadA = [&](int kt) {
#pragma unroll
        for (int i = 0; i < 8; i++) {
            int idx = i * 256 + tid;
            int rrow = idx >> 4, kk = idx & 15;
            int gm = bm + rrow, gk = kt * BK + kk;
            float v = 0.f;
            if (gm < M && gk < K) v = A[(long long)gm * K + gk];
            if (TANH_A) v = tanhf(v);
            ra[i] = v;
        }
    };
    auto loadB = [&](int kt) {
#pragma unroll
        for (int i = 0; i < 8; i++) {
            int idx = i * 256 + tid;
            float v = 0.f;
            if (!TRANS_B) {
                int kk = idx >> 7, n = idx & 127;
                int gk = kt * BK + kk, gn = bn + n;
                if (gk < K && gn < N) v = Bm[(long long)gk * N + gn];
            } else {
                int n = idx >> 4, kk = idx & 15;
                int gn = bn + n, gk = kt * BK + kk;
                if (gn < N && gk < K) v = Bm[(long long)gn * K + gk];
            }
            rb[i] = v;
        }
    };
    auto storeA = [&](int b) {
#pragma unroll
        for (int i = 0; i < 8; i++) {
            int idx = i * 256 + tid;
            As[b][idx & 15][idx >> 4] = ra[i];
        }
    };
    auto storeB = [&](int b) {
#pragma unroll
        for (int i = 0; i < 8; i++) {
            int idx = i * 256 + tid;
            if (!TRANS_B) Bs[b][idx >> 7][idx & 127] = rb[i];
            else          Bs[b][idx & 15][idx >> 4]  = rb[i];
        }
    };

    loadA(0); loadB(0); storeA(0); storeB(0);
    __syncthreads();

    for (int kt = 0; kt < nt; ++kt) {
        const int cur = kt & 1;
        if (kt + 1 < nt) { loadA(kt + 1); loadB(kt + 1); }
#pragma unroll
        for (int kk = 0; kk < BK; ++kk) {
            float af[8], bf[8];
#pragma unroll
            for (int i = 0; i < 8; i++) af[i] = As[cur][kk][m0 + i];
#pragma unroll
            for (int j = 0; j < 8; j++) bf[j] = Bs[cur][kk][n0 + j];
#pragma unroll
            for (int i = 0; i < 8; i++)
#pragma unroll
                for (int j = 0; j < 8; j++) acc[i][j] += af[i] * bf[j];
        }
        if (kt + 1 < nt) { storeA(cur ^ 1); storeB(cur ^ 1); }
        __syncthreads();
    }

#pragma unroll
    for (int i = 0; i < 8; i++) {
        int gm = bm + m0 + i;
        if (gm < M) {
#pragma unroll
            for (int j = 0; j < 8; j++) {
                int gn = bn + n0 + j;
                if (gn < N) {
                    float v = alpha * acc[i][j];
                    if (BETA) v += beta * C[(long long)gm * N + gn];
                    if (BIAS) v += biasp[gn];
                    C[(long long)gm * N + gn] = v;
                }
            }
        }
    }
}

// ---------------- softmax / colsum ------------------------------------------
__global__ void softmax_kernel(float* __restrict__ x, int cols)
{
    long long r = blockIdx.x;
    float* p = x + r * (long long)cols;
    __shared__ float red[256];
    int t = threadIdx.x;
    float mx = -INFINITY;
    for (int c = t; c < cols; c += 256) mx = fmaxf(mx, p[c]);
    red[t] = mx; __syncthreads();
    for (int s = 128; s > 0; s >>= 1) { if (t < s) red[t] = fmaxf(red[t], red[t + s]); __syncthreads(); }
    mx = red[0]; __syncthreads();
    float sum = 0.f;
    for (int c = t; c < cols; c += 256) { float e = expf(p[c] - mx); p[c] = e; sum += e; }
    red[t] = sum; __syncthreads();
    for (int s = 128; s > 0; s >>= 1) { if (t < s) red[t] += red[t + s]; __syncthreads(); }
    float inv = 1.f / red[0];
    for (int c = t; c < cols; c += 256) p[c] *= inv;
}

__global__ void colsum_kernel(const float* __restrict__ x, float* __restrict__ out,
                              int T, int E)
{
    int e = blockIdx.x * blockDim.x + threadIdx.x;
    int b = blockIdx.y;
    const float* p = x + (long long)b * T * E + e;
    float s = 0.f;
    for (int t = 0; t < T; t++) s += p[(long long)t * E];
    out[(long long)b * E + e] = s;
}

// ---------------- host launcher ---------------------------------------------
extern "C" void kernel_launch(void* const* d_in, const int* in_sizes, int n_in,
                              void* d_out, int out_size)
{
    const float* Q    = (const float*)d_in[0];
    const float* K    = (const float*)d_in[1];
    const float* V    = (const float*)d_in[2];
    const float* W_Q  = (const float*)d_in[3];
    const float* W_K  = (const float*)d_in[4];
    const float* W_v  = (const float*)d_in[5];
    const float* W_vq = (const float*)d_in[6];
    const float* W_vk = (const float*)d_in[7];

    float* out  = (float*)d_out;
    float* outQ = out;
    float* outK = out + (long long)B_ * S_ * E_;
    float* f    = out + 2ll * B_ * S_ * E_;

    float *q, *k, *v, *q2, *k2, *vq, *vk, *cs, *cs2;
    cudaGetSymbolAddress((void**)&q,   g_q);
    cudaGetSymbolAddress((void**)&k,   g_k);
    cudaGetSymbolAddress((void**)&v,   g_v);
    cudaGetSymbolAddress((void**)&q2,  g_q2);
    cudaGetSymbolAddress((void**)&k2,  g_k2);
    cudaGetSymbolAddress((void**)&vq,  g_vq);
    cudaGetSymbolAddress((void**)&vk,  g_vk);
    cudaGetSymbolAddress((void**)&cs,  g_cs);
    cudaGetSymbolAddress((void**)&cs2, g_cs2);

    __nv_bfloat16 *Qsh, *Qsl, *Ksh, *Ksl, *WqTh, *WqTl, *WkTh, *WkTl;
    __nv_bfloat16 *qh, *ql, *kh, *kl, *qTh, *qTl, *kTh, *kTl;
    __nv_bfloat16 *fh, *fl, *q2Th, *q2Tl, *k2Th, *k2Tl;
    cudaGetSymbolAddress((void**)&Qsh,  g_Qs_h);  cudaGetSymbolAddress((void**)&Qsl,  g_Qs_l);
    cudaGetSymbolAddress((void**)&Ksh,  g_Ks_h);  cudaGetSymbolAddress((void**)&Ksl,  g_Ks_l);
    cudaGetSymbolAddress((void**)&WqTh, g_WqT_h); cudaGetSymbolAddress((void**)&WqTl, g_WqT_l);
    cudaGetSymbolAddress((void**)&WkTh, g_WkT_h); cudaGetSymbolAddress((void**)&WkTl, g_WkT_l);
    cudaGetSymbolAddress((void**)&qh,   g_qh);    cudaGetSymbolAddress((void**)&ql,   g_ql);
    cudaGetSymbolAddress((void**)&kh,   g_kh);    cudaGetSymbolAddress((void**)&kl,   g_kl);
    cudaGetSymbolAddress((void**)&qTh,  g_qTh);   cudaGetSymbolAddress((void**)&qTl,  g_qTl);
    cudaGetSymbolAddress((void**)&kTh,  g_kTh);   cudaGetSymbolAddress((void**)&kTl,  g_kTl);
    cudaGetSymbolAddress((void**)&fh,   g_fh);    cudaGetSymbolAddress((void**)&fl,   g_fl);
    cudaGetSymbolAddress((void**)&q2Th, g_q2Th);  cudaGetSymbolAddress((void**)&q2Tl, g_q2Tl);
    cudaGetSymbolAddress((void**)&k2Th, g_k2Th);  cudaGetSymbolAddress((void**)&k2Tl, g_k2Tl);

    cudaFuncSetAttribute(hmma_nt<false, false>, cudaFuncAttributeMaxDynamicSharedMemorySize, HM_SMEM_BYTES);
    cudaFuncSetAttribute(hmma_nt<true,  false>, cudaFuncAttributeMaxDynamicSharedMemorySize, HM_SMEM_BYTES);
    cudaFuncSetAttribute(hmma_nt<false, true >, cudaFuncAttributeMaxDynamicSharedMemorySize, HM_SMEM_BYTES);

    const float inv = 1.0f / 32.0f;  // 1/sqrt(1024)
    const long long sQE = (long long)S_ * E_;
    const long long sSS = (long long)S_ * S_;
    const long long sSV = (long long)S_ * SV_;
    const long long nQE = (long long)B_ * S_ * E_;
    const long long nFF = (long long)B_ * S_ * S_;
    dim3 blk(256);

    // ---- stage 0: splits of inputs -----------------------------------------
    split_k<true><<<(int)(nQE / 4 / 256), 256>>>(Q, Qsh, Qsl, nQE);
    split_k<true><<<(int)(nQE / 4 / 256), 256>>>(K, Ksh, Ksl, nQE);
    splitT_k<<<dim3(32, 32, 1), dim3(32, 8)>>>(W_Q, WqTh, WqTl, E_, E_, 0, 0);
    splitT_k<<<dim3(32, 32, 1), dim3(32, 8)>>>(W_K, WkTh, WkTl, E_, E_, 0, 0);

    // ---- stage 1: projections (HMMA) ---------------------------------------
    hmma_nt<false, false><<<dim3(E_/HM_BN, (B_*S_)/HM_BM, 1), 256, HM_SMEM_BYTES>>>(
        Qsh, Qsl, WqTh, WqTl, q, nullptr, B_*S_, E_, E_, 0, 0, 0, 0, 1.f, 0.f);
    hmma_nt<false, false><<<dim3(E_/HM_BN, (B_*S_)/HM_BM, 1), 256, HM_SMEM_BYTES>>>(
        Ksh, Ksl, WkTh, WkTl, k, nullptr, B_*S_, E_, E_, 0, 0, 0, 0, 1.f, 0.f);
    // v = tanh(V)@W_v  (SIMT, small)
    gemm_k<true, false, false, false><<<dim3(8, 2, 1), blk>>>(V, W_v, v, nullptr,
        B_*SV_, E_, E_, 0, 0, 0, 0, 1.f, 0.f);

    // ---- stage 2: splits of q/k, colsum ------------------------------------
    split_k<false><<<(int)(nQE / 4 / 256), 256>>>(q, qh, ql, nQE);
    split_k<false><<<(int)(nQE / 4 / 256), 256>>>(k, kh, kl, nQE);
    splitT_k<<<dim3(E_/32, S_/32, B_), dim3(32, 8)>>>(q, qTh, qTl, S_, E_, sQE, sQE);
    splitT_k<<<dim3(E_/32, S_/32, B_), dim3(32, 8)>>>(k, kTh, kTl, S_, E_, sQE, sQE);
    colsum_kernel<<<dim3(E_/256, B_), 256>>>(k, cs, S_, E_);

    // ---- stage 3: f = softmax(q@k^T / 32) ----------------------------------
    hmma_nt<false, false><<<dim3(S_/HM_BN, S_/HM_BM, B_), 256, HM_SMEM_BYTES>>>(
        qh, ql, kh, kl, f, nullptr, S_, S_, E_, sQE, sQE, sSS, 0, inv, 0.f);
    softmax_kernel<<<B_*S_, 256>>>(f, S_);
    split_k<false><<<(int)(nFF / 4 / 256), 256>>>(f, fh, fl, nFF);

    // ---- small SIMT: vq, vk, q2/k2 base ------------------------------------
    gemm_k<false, true, false, false><<<dim3(1, 16, B_), blk>>>(q, v, vq, nullptr,
        S_, SV_, E_, sQE, (long long)SV_*E_, sSV, 0, inv, 0.f);
    gemm_k<false, true, false, false><<<dim3(1, 16, B_), blk>>>(k, v, vk, nullptr,
        S_, SV_, E_, sQE, (long long)SV_*E_, sSV, 0, inv, 0.f);
    gemm_k<false, false, false, false><<<dim3(8, 16, B_), blk>>>(vq, W_vq, q2, nullptr,
        S_, E_, SV_, sSV, 0, sQE, 0, 1.f, 0.f);
    gemm_k<false, false, false, true><<<dim3(8, 16, B_), blk>>>(vk, W_vk, k2, cs,
        S_, E_, SV_, sSV, 0, sQE, E_, 1.f, 0.f);

    // ---- stage 4: q2 += f@q ; k2 -= f@k (HMMA, B = transposed splits) ------
    hmma_nt<true, false><<<dim3(E_/HM_BN, S_/HM_BM, B_), 256, HM_SMEM_BYTES>>>(
        fh, fl, qTh, qTl, q2, nullptr, S_, E_, S_, sSS, sQE, sQE, 0, 1.f, 1.f);
    hmma_nt<true, false><<<dim3(E_/HM_BN, S_/HM_BM, B_), 256, HM_SMEM_BYTES>>>(
        fh, fl, kTh, kTl, k2, nullptr, S_, E_, S_, sSS, sQE, sQE, 0, -1.f, 1.f);

    // ---- stage 5: outputs ---------------------------------------------------
    splitT_k<<<dim3(E_/32, S_/32, B_), dim3(32, 8)>>>(q2, q2Th, q2Tl, S_, E_, sQE, sQE);
    splitT_k<<<dim3(E_/32, S_/32, B_), dim3(32, 8)>>>(k2, k2Th, k2Tl, S_, E_, sQE, sQE);
    colsum_kernel<<<dim3(E_/256, B_), 256>>>(k2, cs2, S_, E_);

    hmma_nt<false, false><<<dim3(E_/HM_BN, S_/HM_BM, B_), 256, HM_SMEM_BYTES>>>(
        fh, fl, q2Th, q2Tl, outQ, nullptr, S_, E_, S_, sSS, sQE, sQE, 0, 1.f, 0.f);
    hmma_nt<false, true><<<dim3(E_/HM_BN, S_/HM_BM, B_), 256, HM_SMEM_BYTES>>>(
        fh, fl, k2Th, k2Tl, outK, cs2, S_, E_, S_, sSS, sQE, sQE, E_, -1.f, 0.f);

    (void)in_sizes; (void)n_in; (void)out_size;
}